// round 5
// baseline (speedup 1.0000x reference)
#include <cuda_runtime.h>

#define B_DIM 8
#define H_DIM 8
#define P_DIM 4
#define PB 32
#define FEAT 64
#define EMB 32
#define HIN 96
#define GH 32
#define T_DIM 101770
#define TILE_T 128
#define ATT_STRIDE 100   // 96 + 4 pad -> conflict-free LDS.128 across lanes
#define GEN_STRIDE 36    // 32 + 4 pad

// ---------------- device scratch (no allocation allowed) ----------------
__device__ __align__(16) float g_h1[B_DIM * 128];
__device__ __align__(16) float g_hin[PB * HIN];
__device__ __align__(16) float g_hmid[H_DIM * PB * GH];
__device__ __align__(16) float g_gate[B_DIM * H_DIM];

// ---------------- packed fp32 helpers (Blackwell FFMA2) -----------------
static __device__ __forceinline__ unsigned long long ffma2(
    unsigned long long a, unsigned long long b, unsigned long long c) {
    unsigned long long d;
    asm("fma.rn.f32x2 %0, %1, %2, %3;" : "=l"(d) : "l"(a), "l"(b), "l"(c));
    return d;
}
static __device__ __forceinline__ float2 upk(unsigned long long a) {
    float2 f;
    asm("mov.b64 {%0, %1}, %2;" : "=f"(f.x), "=f"(f.y) : "l"(a));
    return f;
}

// ---------------- setup 1: h1 = relu(x @ fe_W1^T + fe_b1)  [8,128] -------
__global__ void k_setup1(const float* __restrict__ x,
                         const float* __restrict__ W1,
                         const float* __restrict__ b1) {
    int b = blockIdx.x, j = threadIdx.x;               // 8 blocks x 128 threads
    const float4* xr = (const float4*)(x + b * 784);
    const float4* wr = (const float4*)(W1 + j * 784);
    float s0 = 0.f, s1 = 0.f;
#pragma unroll 4
    for (int i = 0; i < 196; i += 2) {
        float4 a0 = xr[i], w0 = wr[i];
        s0 += a0.x * w0.x + a0.y * w0.y + a0.z * w0.z + a0.w * w0.w;
        float4 a1 = xr[i + 1], w1 = wr[i + 1];
        s1 += a1.x * w1.x + a1.y * w1.y + a1.z * w1.z + a1.w * w1.w;
    }
    g_h1[b * 128 + j] = fmaxf(s0 + s1 + b1[j], 0.f);
}

// ---------------- setup 2: feats, gate (softmax over heads), hin ---------
__global__ void k_setup2(const float* __restrict__ W2,
                         const float* __restrict__ b2,
                         const float* __restrict__ embeds,
                         const float* __restrict__ gateW,
                         const float* __restrict__ gateB) {
    __shared__ float sh1[B_DIM * 128];
    __shared__ float sfe[B_DIM * FEAT];
    int tid = threadIdx.x;                              // 128 threads
    for (int i = tid; i < B_DIM * 128; i += 128) sh1[i] = g_h1[i];
    __syncthreads();
    // feats = h1 @ fe_W2^T + fe_b2   [8,64]
    for (int o = tid; o < B_DIM * FEAT; o += 128) {
        int b = o >> 6, f = o & 63;
        const float* w = W2 + f * 128;
        const float* hh = sh1 + b * 128;
        float s = 0.f;
#pragma unroll 8
        for (int k = 0; k < 128; k++) s += hh[k] * w[k];
        sfe[o] = s + b2[f];
    }
    __syncthreads();
    // gate[b][h] = softmax_h(feats[b] . gateW[h] + gateB[h])
    if (tid < B_DIM) {
        int b = tid;
        float l[H_DIM];
        float m = -1e30f;
        for (int h = 0; h < H_DIM; h++) {
            float s = gateB[h];
            for (int f = 0; f < FEAT; f++) s += sfe[b * FEAT + f] * gateW[h * FEAT + f];
            l[h] = s;
            m = fmaxf(m, s);
        }
        float sum = 0.f;
        for (int h = 0; h < H_DIM; h++) { l[h] = expf(l[h] - m); sum += l[h]; }
        float inv = 1.f / sum;
        for (int h = 0; h < H_DIM; h++) g_gate[b * H_DIM + h] = l[h] * inv;
    }
    // hin[pb=p*8+b][k] = k<64 ? feats[b][k] : embeds[p][k-64]
    for (int i = tid; i < PB * HIN; i += 128) {
        int pb = i / HIN, k = i % HIN;
        int p = pb >> 3, bb = pb & 7;
        g_hin[i] = (k < FEAT) ? sfe[bb * FEAT + k] : embeds[p * EMB + (k - FEAT)];
    }
}

// ---------------- setup 3: hmid = relu(hin @ gen_W1^T + gen_b1) ----------
__global__ void k_setup3(const float* __restrict__ W1,
                         const float* __restrict__ b1) {
    int idx = blockIdx.x * blockDim.x + threadIdx.x;    // 32 x 256 = 8192
    int h = idx >> 10, r = idx & 1023, pb = r >> 5, j = r & 31;
    const float4* w = (const float4*)(W1 + (size_t)(h * GH + j) * HIN);
    const float4* hv = (const float4*)(g_hin + pb * HIN);
    float s = 0.f;
#pragma unroll
    for (int i = 0; i < HIN / 4; i++) {
        float4 a = hv[i], ww = w[i];
        s += a.x * ww.x + a.y * ww.y + a.z * ww.z + a.w * ww.w;
    }
    s += b1[h * GH + j];
    g_hmid[(h * PB + pb) * GH + j] = fmaxf(s, 0.f);
}

// ---------------- main fused kernel --------------------------------------
__global__ __launch_bounds__(TILE_T) void k_main(
    const float* __restrict__ attW, const float* __restrict__ attB,
    const float* __restrict__ genW2, const float* __restrict__ genB2,
    float* __restrict__ out) {
    extern __shared__ float smem[];
    float* sAtt = smem;                                  // TILE_T*100
    float* sGen = sAtt + TILE_T * ATT_STRIDE;            // TILE_T*36
    float* sHin = sGen + TILE_T * GEN_STRIDE;            // 32*96
    float* sHmid = sHin + PB * HIN;                      // 32*32
    float* sGate = sHmid + PB * GH;                      // 64

    int tid = threadIdx.x;
    for (int i = tid; i < PB * HIN; i += TILE_T) sHin[i] = g_hin[i];
    if (tid < B_DIM * H_DIM) sGate[tid] = g_gate[tid];

    const int numTiles = (T_DIM + TILE_T - 1) / TILE_T;  // 796
    for (int tile = blockIdx.x; tile < numTiles; tile += gridDim.x) {
        int t0 = tile * TILE_T;
        int t = t0 + tid;
        bool valid = t < T_DIM;
        int nrow = min(TILE_T, T_DIM - t0);

        float comb[PB];
#pragma unroll
        for (int pb = 0; pb < PB; ++pb) comb[pb] = 0.f;

        for (int h = 0; h < H_DIM; ++h) {
            __syncthreads();  // previous compute done before tiles are overwritten
            // ---- stage att_W tile (coalesced GMEM -> padded SMEM) ----
            {
                const float4* src = (const float4*)(attW + (size_t)(h * T_DIM + t0) * HIN);
                int nf4 = nrow * (HIN / 4);
#pragma unroll
                for (int it = 0; it < (HIN / 4); ++it) {
                    int i = tid + it * TILE_T;
                    if (i < nf4) {
                        float4 v = src[i];
                        int r = i / (HIN / 4), c = i % (HIN / 4);
                        *(float4*)&sAtt[r * ATT_STRIDE + c * 4] = v;
                    }
                }
            }
            // ---- stage gen_W2 tile ----
            {
                const float4* src = (const float4*)(genW2 + (size_t)(h * T_DIM + t0) * GH);
                int nf4 = nrow * (GH / 4);
#pragma unroll
                for (int it = 0; it < (GH / 4); ++it) {
                    int i = tid + it * TILE_T;
                    if (i < nf4) {
                        float4 v = src[i];
                        int r = i / (GH / 4), c = i % (GH / 4);
                        *(float4*)&sGen[r * GEN_STRIDE + c * 4] = v;
                    }
                }
            }
            // ---- stage hmid[h] (1024 floats) ----
            {
                const float4* src = (const float4*)(g_hmid + h * PB * GH);
#pragma unroll
                for (int it = 0; it < 2; ++it) {
                    ((float4*)sHmid)[tid + it * TILE_T] = src[tid + it * TILE_T];
                }
            }
            __syncthreads();

            if (valid) {
                const float* myAtt = sAtt + tid * ATT_STRIDE;
                const float* myGen = sGen + tid * GEN_STRIDE;
                unsigned long long acc[PB];

                // -------- gen GEMM: g[pb] = hmid[h,pb,:] . genW2[h,t,:] --------
#pragma unroll
                for (int pb = 0; pb < PB; ++pb) acc[pb] = 0ull;
#pragma unroll 4
                for (int k4 = 0; k4 < GH / 4; ++k4) {
                    ulonglong2 w = *(const ulonglong2*)&myGen[k4 * 4];
#pragma unroll
                    for (int pb = 0; pb < PB; ++pb) {
                        ulonglong2 hv = *(const ulonglong2*)&sHmid[pb * GH + k4 * 4];
                        acc[pb] = ffma2(hv.x, w.x, acc[pb]);
                        acc[pb] = ffma2(hv.y, w.y, acc[pb]);
                    }
                }
                float gb = genB2[(size_t)h * T_DIM + t];
                float ab = attB[(size_t)h * T_DIM + t];
                float gv[PB];
#pragma unroll
                for (int pb = 0; pb < PB; ++pb) {
                    float2 f = upk(acc[pb]);
                    gv[pb] = f.x + f.y + gb;
                    acc[pb] = 0ull;
                }
                // -------- att GEMM: a[pb] = hin[pb,:] . attW[h,t,:] --------
#pragma unroll 4
                for (int k4 = 0; k4 < HIN / 4; ++k4) {
                    ulonglong2 w = *(const ulonglong2*)&myAtt[k4 * 4];
#pragma unroll
                    for (int pb = 0; pb < PB; ++pb) {
                        ulonglong2 hv = *(const ulonglong2*)&sHin[pb * HIN + k4 * 4];
                        acc[pb] = ffma2(hv.x, w.x, acc[pb]);
                        acc[pb] = ffma2(hv.y, w.y, acc[pb]);
                    }
                }
                // -------- sigmoid + gated combine (note gate[h, b] indexing) ----
#pragma unroll
                for (int pb = 0; pb < PB; ++pb) {
                    float2 f = upk(acc[pb]);
                    float a = f.x + f.y + ab;
                    float imp = 1.0f / (1.0f + __expf(-a));
                    comb[pb] = fmaf(sGate[h * B_DIM + (pb & 7)] * gv[pb], imp, comb[pb]);
                }
            }
        }
        if (valid) {
#pragma unroll
            for (int pb = 0; pb < PB; ++pb) {
                int p = pb >> 3, bb = pb & 7;
                out[(size_t)bb * (P_DIM * T_DIM) + (size_t)p * T_DIM + t] = comb[pb];
            }
        }
    }
}

// ---------------- launch ----------------
extern "C" void kernel_launch(void* const* d_in, const int* in_sizes, int n_in,
                              void* d_out, int out_size) {
    const float* x      = (const float*)d_in[0];
    const float* fe_W1  = (const float*)d_in[1];
    const float* fe_b1  = (const float*)d_in[2];
    const float* fe_W2  = (const float*)d_in[3];
    const float* fe_b2  = (const float*)d_in[4];
    const float* embeds = (const float*)d_in[5];
    const float* gen_W1 = (const float*)d_in[6];
    const float* gen_b1 = (const float*)d_in[7];
    const float* gen_W2 = (const float*)d_in[8];
    const float* gen_b2 = (const float*)d_in[9];
    const float* att_W  = (const float*)d_in[10];
    const float* att_b  = (const float*)d_in[11];
    const float* gate_W = (const float*)d_in[12];
    const float* gate_b = (const float*)d_in[13];
    float* out = (float*)d_out;

    size_t smem = (size_t)(TILE_T * ATT_STRIDE + TILE_T * GEN_STRIDE +
                           PB * HIN + PB * GH + B_DIM * H_DIM) * sizeof(float);
    cudaFuncSetAttribute(k_main, cudaFuncAttributeMaxDynamicSharedMemorySize, (int)smem);

    k_setup1<<<B_DIM, 128>>>(x, fe_W1, fe_b1);
    k_setup2<<<1, 128>>>(fe_W2, fe_b2, embeds, gate_W, gate_b);
    k_setup3<<<32, 256>>>(gen_W1, gen_b1);
    k_main<<<304, TILE_T, smem>>>(att_W, att_b, gen_W2, gen_b2, out);
}

// round 6
// speedup vs baseline: 1.5122x; 1.5122x over previous
#include <cuda_runtime.h>

#define B_DIM 8
#define H_DIM 8
#define P_DIM 4
#define PB 32
#define FEAT 64
#define EMB 32
#define HIN 96
#define GH 32
#define T_DIM 101770
#define TILE_T 128
#define NUM_TILES ((T_DIM + TILE_T - 1) / TILE_T)   // 796
#define ATT_STRIDE 100   // 96 + 4 pad -> conflict-free LDS.128 (stride/4 odd)
#define GEN_STRIDE 36    // 32 + 4 pad
#define GRID_MAIN 296    // 2 blocks per SM exactly

// ---------------- device scratch (no allocation allowed) ----------------
__device__ __align__(16) float g_h1[B_DIM * 128];
__device__ __align__(16) float g_hin[PB * HIN];
__device__ __align__(16) float g_hmid[H_DIM * PB * GH];
__device__ __align__(16) float g_gate[B_DIM * H_DIM];

// ---------------- packed fp32 helpers (Blackwell FFMA2) -----------------
static __device__ __forceinline__ unsigned long long ffma2(
    unsigned long long a, unsigned long long b, unsigned long long c) {
    unsigned long long d;
    asm("fma.rn.f32x2 %0, %1, %2, %3;" : "=l"(d) : "l"(a), "l"(b), "l"(c));
    return d;
}
static __device__ __forceinline__ float2 upk(unsigned long long a) {
    float2 f;
    asm("mov.b64 {%0, %1}, %2;" : "=f"(f.x), "=f"(f.y) : "l"(a));
    return f;
}

// ---------------- setup 1: h1 = relu(x @ fe_W1^T + fe_b1)  [8,128] -------
__global__ void k_setup1(const float* __restrict__ x,
                         const float* __restrict__ W1,
                         const float* __restrict__ b1) {
    int b = blockIdx.x, j = threadIdx.x;               // 8 blocks x 128 threads
    const float4* xr = (const float4*)(x + b * 784);
    const float4* wr = (const float4*)(W1 + j * 784);
    float s0 = 0.f, s1 = 0.f;
#pragma unroll 4
    for (int i = 0; i < 196; i += 2) {
        float4 a0 = xr[i], w0 = wr[i];
        s0 += a0.x * w0.x + a0.y * w0.y + a0.z * w0.z + a0.w * w0.w;
        float4 a1 = xr[i + 1], w1 = wr[i + 1];
        s1 += a1.x * w1.x + a1.y * w1.y + a1.z * w1.z + a1.w * w1.w;
    }
    g_h1[b * 128 + j] = fmaxf(s0 + s1 + b1[j], 0.f);
}

// ---------------- setup 2: feats, gate (softmax over heads), hin ---------
__global__ void k_setup2(const float* __restrict__ W2,
                         const float* __restrict__ b2,
                         const float* __restrict__ embeds,
                         const float* __restrict__ gateW,
                         const float* __restrict__ gateB) {
    __shared__ float sh1[B_DIM * 128];
    __shared__ float sfe[B_DIM * FEAT];
    int tid = threadIdx.x;                              // 128 threads
    for (int i = tid; i < B_DIM * 128; i += 128) sh1[i] = g_h1[i];
    __syncthreads();
    for (int o = tid; o < B_DIM * FEAT; o += 128) {
        int b = o >> 6, f = o & 63;
        const float* w = W2 + f * 128;
        const float* hh = sh1 + b * 128;
        float s = 0.f;
#pragma unroll 8
        for (int k = 0; k < 128; k++) s += hh[k] * w[k];
        sfe[o] = s + b2[f];
    }
    __syncthreads();
    if (tid < B_DIM) {
        int b = tid;
        float l[H_DIM];
        float m = -1e30f;
        for (int h = 0; h < H_DIM; h++) {
            float s = gateB[h];
            for (int f = 0; f < FEAT; f++) s += sfe[b * FEAT + f] * gateW[h * FEAT + f];
            l[h] = s;
            m = fmaxf(m, s);
        }
        float sum = 0.f;
        for (int h = 0; h < H_DIM; h++) { l[h] = expf(l[h] - m); sum += l[h]; }
        float inv = 1.f / sum;
        for (int h = 0; h < H_DIM; h++) g_gate[b * H_DIM + h] = l[h] * inv;
    }
    for (int i = tid; i < PB * HIN; i += 128) {
        int pb = i / HIN, k = i % HIN;
        int p = pb >> 3, bb = pb & 7;
        g_hin[i] = (k < FEAT) ? sfe[bb * FEAT + k] : embeds[p * EMB + (k - FEAT)];
    }
}

// ---------------- setup 3: hmid = relu(hin @ gen_W1^T + gen_b1) ----------
__global__ void k_setup3(const float* __restrict__ W1,
                         const float* __restrict__ b1) {
    int idx = blockIdx.x * blockDim.x + threadIdx.x;    // 32 x 256 = 8192
    int h = idx >> 10, r = idx & 1023, pb = r >> 5, j = r & 31;
    const float4* w = (const float4*)(W1 + (size_t)(h * GH + j) * HIN);
    const float4* hv = (const float4*)(g_hin + pb * HIN);
    float s = 0.f;
#pragma unroll
    for (int i = 0; i < HIN / 4; i++) {
        float4 a = hv[i], ww = w[i];
        s += a.x * ww.x + a.y * ww.y + a.z * ww.z + a.w * ww.w;
    }
    s += b1[h * GH + j];
    g_hmid[(h * PB + pb) * GH + j] = fmaxf(s, 0.f);
}

// ---------------- main fused kernel --------------------------------------
// Block = 128 threads: 32 t-lanes x 4 pb-groups.
// Each thread: 4 t (t0 + lane + 32*jt) x 8 pb (wpb*8 + j).
__global__ __launch_bounds__(128, 2) void k_main(
    const float* __restrict__ attW, const float* __restrict__ attB,
    const float* __restrict__ genW2, const float* __restrict__ genB2,
    float* __restrict__ out) {
    extern __shared__ float smem[];
    float* sAtt  = smem;                                 // 128*100
    float* sGen  = sAtt + TILE_T * ATT_STRIDE;           // 128*36
    float* sHin  = sGen + TILE_T * GEN_STRIDE;           // 32*96
    float* sHmid = sHin + PB * HIN;                      // 32*32
    float* sGate = sHmid + PB * GH;                      // 64
    float* sGb   = sGate + B_DIM * H_DIM;                // 128
    float* sAb   = sGb + TILE_T;                         // 128

    const int tid = threadIdx.x;
    const int lane = tid & 31;
    const int wpb = tid >> 5;                            // pb group 0..3

    for (int i = tid; i < PB * HIN; i += 128) sHin[i] = g_hin[i];
    if (tid < B_DIM * H_DIM) sGate[tid] = g_gate[tid];

    for (int tile = blockIdx.x; tile < NUM_TILES; tile += gridDim.x) {
        const int t0 = tile * TILE_T;
        const int nrow = min(TILE_T, T_DIM - t0);
        const bool full = (nrow == TILE_T);

        float comb[4][8];
#pragma unroll
        for (int jt = 0; jt < 4; ++jt)
#pragma unroll
            for (int j = 0; j < 8; ++j) comb[jt][j] = 0.f;

        for (int h = 0; h < H_DIM; ++h) {
            __syncthreads();   // previous compute done before overwrite
            // ---------- stage tiles (coalesced GMEM -> padded SMEM) ----------
            const float4* srcA = (const float4*)(attW + (size_t)(h * T_DIM + t0) * HIN);
            const float4* srcG = (const float4*)(genW2 + (size_t)(h * T_DIM + t0) * GH);
            const float4* srcM = (const float4*)(g_hmid + h * PB * GH);
            if (full) {
#pragma unroll
                for (int it = 0; it < HIN / 4; ++it) {           // 24 iters
                    int i = tid + it * TILE_T;
                    float4 v = srcA[i];
                    int r = i / (HIN / 4), c = i % (HIN / 4);
                    *(float4*)&sAtt[r * ATT_STRIDE + c * 4] = v;
                }
#pragma unroll
                for (int it = 0; it < GH / 4; ++it) {            // 8 iters
                    int i = tid + it * TILE_T;
                    float4 v = srcG[i];
                    int r = i >> 3, c = i & 7;
                    *(float4*)&sGen[r * GEN_STRIDE + c * 4] = v;
                }
                sGb[tid] = genB2[(size_t)h * T_DIM + t0 + tid];
                sAb[tid] = attB[(size_t)h * T_DIM + t0 + tid];
            } else {
                int nA = nrow * (HIN / 4);
#pragma unroll
                for (int it = 0; it < HIN / 4; ++it) {
                    int i = tid + it * TILE_T;
                    if (i < nA) {
                        float4 v = srcA[i];
                        int r = i / (HIN / 4), c = i % (HIN / 4);
                        *(float4*)&sAtt[r * ATT_STRIDE + c * 4] = v;
                    }
                }
                int nG = nrow * (GH / 4);
#pragma unroll
                for (int it = 0; it < GH / 4; ++it) {
                    int i = tid + it * TILE_T;
                    if (i < nG) {
                        float4 v = srcG[i];
                        int r = i >> 3, c = i & 7;
                        *(float4*)&sGen[r * GEN_STRIDE + c * 4] = v;
                    }
                }
                if (tid < nrow) {
                    sGb[tid] = genB2[(size_t)h * T_DIM + t0 + tid];
                    sAb[tid] = attB[(size_t)h * T_DIM + t0 + tid];
                }
            }
#pragma unroll
            for (int it = 0; it < 2; ++it)
                ((float4*)sHmid)[tid + it * TILE_T] = srcM[tid + it * TILE_T];
            __syncthreads();

            // ---------- gen GEMM: gv[jt][j] = hmid[h,pb,:] . genW2[h,t,:] ----
            unsigned long long acc[4][8];
#pragma unroll
            for (int jt = 0; jt < 4; ++jt)
#pragma unroll
                for (int j = 0; j < 8; ++j) acc[jt][j] = 0ull;
#pragma unroll
            for (int k4 = 0; k4 < GH / 4; ++k4) {
                ulonglong2 w[4];
#pragma unroll
                for (int jt = 0; jt < 4; ++jt)
                    w[jt] = *(const ulonglong2*)&sGen[(lane + 32 * jt) * GEN_STRIDE + k4 * 4];
#pragma unroll
                for (int j = 0; j < 8; ++j) {
                    ulonglong2 hv = *(const ulonglong2*)&sHmid[(wpb * 8 + j) * GH + k4 * 4];
#pragma unroll
                    for (int jt = 0; jt < 4; ++jt) {
                        acc[jt][j] = ffma2(hv.x, w[jt].x, acc[jt][j]);
                        acc[jt][j] = ffma2(hv.y, w[jt].y, acc[jt][j]);
                    }
                }
            }
            float gb[4], ab[4];
#pragma unroll
            for (int jt = 0; jt < 4; ++jt) {
                gb[jt] = sGb[lane + 32 * jt];
                ab[jt] = sAb[lane + 32 * jt];
            }
            float gv[4][8];
#pragma unroll
            for (int jt = 0; jt < 4; ++jt)
#pragma unroll
                for (int j = 0; j < 8; ++j) {
                    float2 f = upk(acc[jt][j]);
                    gv[jt][j] = f.x + f.y + gb[jt];
                    acc[jt][j] = 0ull;
                }

            // ---------- att GEMM: a[jt][j] = hin[pb,:] . attW[h,t,:] --------
#pragma unroll 4
            for (int k4 = 0; k4 < HIN / 4; ++k4) {
                ulonglong2 w[4];
#pragma unroll
                for (int jt = 0; jt < 4; ++jt)
                    w[jt] = *(const ulonglong2*)&sAtt[(lane + 32 * jt) * ATT_STRIDE + k4 * 4];
#pragma unroll
                for (int j = 0; j < 8; ++j) {
                    ulonglong2 hv = *(const ulonglong2*)&sHin[(wpb * 8 + j) * HIN + k4 * 4];
#pragma unroll
                    for (int jt = 0; jt < 4; ++jt) {
                        acc[jt][j] = ffma2(hv.x, w[jt].x, acc[jt][j]);
                        acc[jt][j] = ffma2(hv.y, w[jt].y, acc[jt][j]);
                    }
                }
            }

            // ---------- sigmoid + gated combine (gate[h, b], b = j) ---------
            float gt[8];
#pragma unroll
            for (int j = 0; j < 8; ++j) gt[j] = sGate[h * B_DIM + j];
#pragma unroll
            for (int jt = 0; jt < 4; ++jt)
#pragma unroll
                for (int j = 0; j < 8; ++j) {
                    float2 f = upk(acc[jt][j]);
                    float a = f.x + f.y + ab[jt];
                    float imp = 1.0f / (1.0f + __expf(-a));
                    comb[jt][j] = fmaf(gt[j] * gv[jt][j], imp, comb[jt][j]);
                }
        }

        // ---------- write out: p = wpb, b = j, coalesced over lanes ----------
#pragma unroll
        for (int jt = 0; jt < 4; ++jt) {
            int t = t0 + lane + 32 * jt;
            if (t < T_DIM) {
#pragma unroll
                for (int j = 0; j < 8; ++j)
                    out[(size_t)(j * P_DIM + wpb) * T_DIM + t] = comb[jt][j];
            }
        }
    }
}

// ---------------- launch ----------------
extern "C" void kernel_launch(void* const* d_in, const int* in_sizes, int n_in,
                              void* d_out, int out_size) {
    const float* x      = (const float*)d_in[0];
    const float* fe_W1  = (const float*)d_in[1];
    const float* fe_b1  = (const float*)d_in[2];
    const float* fe_W2  = (const float*)d_in[3];
    const float* fe_b2  = (const float*)d_in[4];
    const float* embeds = (const float*)d_in[5];
    const float* gen_W1 = (const float*)d_in[6];
    const float* gen_b1 = (const float*)d_in[7];
    const float* gen_W2 = (const float*)d_in[8];
    const float* gen_b2 = (const float*)d_in[9];
    const float* att_W  = (const float*)d_in[10];
    const float* att_b  = (const float*)d_in[11];
    const float* gate_W = (const float*)d_in[12];
    const float* gate_b = (const float*)d_in[13];
    float* out = (float*)d_out;

    size_t smem = (size_t)(TILE_T * ATT_STRIDE + TILE_T * GEN_STRIDE +
                           PB * HIN + PB * GH + B_DIM * H_DIM +
                           TILE_T + TILE_T) * sizeof(float);
    cudaFuncSetAttribute(k_main, cudaFuncAttributeMaxDynamicSharedMemorySize, (int)smem);

    k_setup1<<<B_DIM, 128>>>(x, fe_W1, fe_b1);
    k_setup2<<<1, 128>>>(fe_W2, fe_b2, embeds, gate_W, gate_b);
    k_setup3<<<32, 256>>>(gen_W1, gen_b1);
    k_main<<<GRID_MAIN, 128, smem>>>(att_W, att_b, gen_W2, gen_b2, out);
}